// round 3
// baseline (speedup 1.0000x reference)
#include <cuda_runtime.h>
#include <cstdint>

#define B_   8
#define L_   1024
#define D_   512
#define H_   8
#define DK_  64
#define KW_  7
#define PAD_ 3
#define NCAT 448   /* KW*DK */

// ---------------- scratch (device globals; no runtime allocation) ----------
__device__ float g_qs[B_*L_*D_];
__device__ float g_ks[B_*L_*D_];
__device__ float g_vs[B_*L_*D_];
__device__ float g_qcat[(size_t)B_*H_*L_*NCAT];
__device__ float g_rowbias[B_*H_*L_];
__device__ float g_bcat[H_*NCAT];
__device__ float g_ctx[B_*L_*D_];

// ---------------------------------------------------------------------------
// Generic 128x128 SGEMM, C[M,N] = A[M,K] @ W[N,K]^T + bias[N]
// Requires M%128==0, N%128==0, K%16==0, lda=K, ldw=K, ldc=N.
// Used for the 4 projection GEMMs (8192 x 512 x 512).
// ---------------------------------------------------------------------------
__global__ __launch_bounds__(256) void sgemm_nt_kernel(
    const float* __restrict__ A, const float* __restrict__ W,
    const float* __restrict__ bias, float* __restrict__ C,
    int M, int N, int K)
{
    __shared__ float As[16][128];
    __shared__ float Bs[16][128];
    const int bm = blockIdx.y * 128;
    const int bn = blockIdx.x * 128;
    const int tid = threadIdx.x;
    const int ty = tid >> 4, tx = tid & 15;
    const int lr = tid >> 2;          // 0..63
    const int lc = (tid & 3) << 2;    // 0,4,8,12

    float acc[8][8];
#pragma unroll
    for (int i = 0; i < 8; i++)
#pragma unroll
        for (int j = 0; j < 8; j++) acc[i][j] = 0.f;

    for (int k0 = 0; k0 < K; k0 += 16) {
#pragma unroll
        for (int s = 0; s < 2; s++) {
            int row = lr + s * 64;
            float4 va = *(const float4*)(A + (size_t)(bm + row) * K + k0 + lc);
            As[lc+0][row] = va.x; As[lc+1][row] = va.y;
            As[lc+2][row] = va.z; As[lc+3][row] = va.w;
            float4 vb = *(const float4*)(W + (size_t)(bn + row) * K + k0 + lc);
            Bs[lc+0][row] = vb.x; Bs[lc+1][row] = vb.y;
            Bs[lc+2][row] = vb.z; Bs[lc+3][row] = vb.w;
        }
        __syncthreads();
#pragma unroll
        for (int kk = 0; kk < 16; kk++) {
            float ra[8], rb[8];
            *(float4*)(ra)   = *(const float4*)&As[kk][ty*8];
            *(float4*)(ra+4) = *(const float4*)&As[kk][ty*8+4];
            *(float4*)(rb)   = *(const float4*)&Bs[kk][tx*4];
            *(float4*)(rb+4) = *(const float4*)&Bs[kk][64 + tx*4];
#pragma unroll
            for (int i = 0; i < 8; i++)
#pragma unroll
                for (int j = 0; j < 8; j++)
                    acc[i][j] = fmaf(ra[i], rb[j], acc[i][j]);
        }
        __syncthreads();
    }

    float4 b0 = *(const float4*)(bias + bn + tx*4);
    float4 b1 = *(const float4*)(bias + bn + 64 + tx*4);
#pragma unroll
    for (int i = 0; i < 8; i++) {
        size_t ro = (size_t)(bm + ty*8 + i) * N + bn;
        float4 o0 = make_float4(acc[i][0]+b0.x, acc[i][1]+b0.y,
                                acc[i][2]+b0.z, acc[i][3]+b0.w);
        float4 o1 = make_float4(acc[i][4]+b1.x, acc[i][5]+b1.y,
                                acc[i][6]+b1.z, acc[i][7]+b1.w);
        *(float4*)(C + ro + tx*4)      = o0;
        *(float4*)(C + ro + 64 + tx*4) = o1;
    }
}

// ---------------------------------------------------------------------------
// bcat[h, t*64+c] = bker[h,c,t]      (q_s already contains bq; do NOT re-add
//                                     bq through Wker — that double-counts)
// ---------------------------------------------------------------------------
__global__ void bcat_kernel(const float* __restrict__ bker)
{
    int n = blockIdx.x * blockDim.x + threadIdx.x;
    if (n >= H_ * NCAT) return;
    int h = n / NCAT, r = n % NCAT, t = r / DK_, c = r % DK_;
    g_bcat[n] = bker[(size_t)(h*DK_ + c) * KW_ + t];
}

// ---------------------------------------------------------------------------
// rowbias[b,h,i] = (q_s[b,h,i,:]·Wqb[h] + bqb[h] + bias_b[h]) / 8
// one warp per row
// ---------------------------------------------------------------------------
__global__ void rowbias_kernel(const float* __restrict__ Wqb,
                               const float* __restrict__ bqb,
                               const float* __restrict__ bias_b)
{
    int warp = (blockIdx.x * blockDim.x + threadIdx.x) >> 5;
    int lane = threadIdx.x & 31;
    if (warp >= B_*H_*L_) return;
    int i = warp & (L_-1);
    int bh = warp >> 10;
    int h = bh & (H_-1), b = bh >> 3;
    const float* qrow = g_qs + ((size_t)(b*L_ + i)) * D_ + h*DK_;
    const float* w = Wqb + h*DK_;
    float s = qrow[lane]*w[lane] + qrow[lane+32]*w[lane+32];
#pragma unroll
    for (int o = 16; o; o >>= 1) s += __shfl_xor_sync(0xffffffffu, s, o);
    if (lane == 0)
        g_rowbias[warp] = (s + bqb[h] + bias_b[h]) * 0.125f;
}

// ---------------------------------------------------------------------------
// Qcat: per (b,h): Qcat[i, n=t*64+c] = sum_d q_s[i,d] * Wker[h,c,t,d] + bcat
// B operand row n has K contiguous (NT): Wker[h,c,t,:] at (h*64+c)*448 + t*64
// grid (4, 8, 64)
// ---------------------------------------------------------------------------
__global__ __launch_bounds__(256) void qcat_kernel(const float* __restrict__ Wker)
{
    const int z = blockIdx.z;
    const int b = z >> 3, h = z & 7;
    const int bm = blockIdx.y * 128;
    const int bn = blockIdx.x * 128;
    const int tid = threadIdx.x;
    const int ty = tid >> 4, tx = tid & 15;

    __shared__ float As[16][128];
    __shared__ float Bs[16][128];

    const float* A = g_qs + (size_t)b * L_ * D_ + h * DK_;     // lda=512, K=64
    const float* W = Wker + (size_t)h * DK_ * NCAT;            // head base

    float acc[8][8];
#pragma unroll
    for (int i = 0; i < 8; i++)
#pragma unroll
        for (int j = 0; j < 8; j++) acc[i][j] = 0.f;

    const int lr = tid >> 2, lc = (tid & 3) << 2;

    for (int k0 = 0; k0 < DK_; k0 += 16) {
#pragma unroll
        for (int s = 0; s < 2; s++) {
            int row = lr + s * 64;
            float4 va = *(const float4*)(A + (size_t)(bm + row) * D_ + k0 + lc);
            As[lc+0][row] = va.x; As[lc+1][row] = va.y;
            As[lc+2][row] = va.z; As[lc+3][row] = va.w;
        }
        // B tile: Bs[k][n], 16 k x 128 n; per output-n the d-span is contiguous
        for (int idx = tid; idx < 512; idx += 256) {
            int nloc = idx >> 2;          // 0..127
            int kl   = (idx & 3) << 2;    // 0,4,8,12
            int gn = bn + nloc;
            float4 vb = make_float4(0,0,0,0);
            if (gn < NCAT) {
                int t = gn >> 6, c = gn & 63;
                vb = *(const float4*)(W + (size_t)c * NCAT + t * DK_ + k0 + kl);
            }
            Bs[kl+0][nloc] = vb.x; Bs[kl+1][nloc] = vb.y;
            Bs[kl+2][nloc] = vb.z; Bs[kl+3][nloc] = vb.w;
        }
        __syncthreads();
#pragma unroll
        for (int kk = 0; kk < 16; kk++) {
            float ra[8], rb[8];
            *(float4*)(ra)   = *(const float4*)&As[kk][ty*8];
            *(float4*)(ra+4) = *(const float4*)&As[kk][ty*8+4];
            *(float4*)(rb)   = *(const float4*)&Bs[kk][tx*4];
            *(float4*)(rb+4) = *(const float4*)&Bs[kk][64 + tx*4];
#pragma unroll
            for (int i = 0; i < 8; i++)
#pragma unroll
                for (int j = 0; j < 8; j++)
                    acc[i][j] = fmaf(ra[i], rb[j], acc[i][j]);
        }
        __syncthreads();
    }

    float* C = g_qcat + (size_t)z * L_ * NCAT;
    int c0g = bn + tx*4, c1g = bn + 64 + tx*4;
    float4 b0 = make_float4(0,0,0,0), b1 = make_float4(0,0,0,0);
    if (c0g < NCAT) b0 = *(const float4*)(g_bcat + h*NCAT + c0g);
    if (c1g < NCAT) b1 = *(const float4*)(g_bcat + h*NCAT + c1g);
#pragma unroll
    for (int i = 0; i < 8; i++) {
        size_t ro = (size_t)(bm + ty*8 + i) * NCAT;
        if (c0g < NCAT) {
            float4 o = make_float4(acc[i][0]+b0.x, acc[i][1]+b0.y,
                                   acc[i][2]+b0.z, acc[i][3]+b0.w);
            *(float4*)(C + ro + c0g) = o;
        }
        if (c1g < NCAT) {
            float4 o = make_float4(acc[i][4]+b1.x, acc[i][5]+b1.y,
                                   acc[i][6]+b1.z, acc[i][7]+b1.w);
            *(float4*)(C + ro + c1g) = o;
        }
    }
}

// ---------------------------------------------------------------------------
// Logits: per (b,h): S[i,j] = (Qcat[i,:448]·Kcat[j,:448])/8 + rowbias[i]
// Kcat[j, t*64+c] = k_s[j+t-3, c]  (zero outside [0,L))
// B operand held as transposed smem tile ksT[c][jl], jl<->global j0+jl-3,
// so the t-shift is just a +t column offset. grid (8, 8, 64).
// Writes RAW logits into the attn output region.
// ---------------------------------------------------------------------------
__global__ __launch_bounds__(256) void logits_kernel(float* __restrict__ attn)
{
    const int z = blockIdx.z;
    const int b = z >> 3, h = z & 7;
    const int i0 = blockIdx.y * 128;
    const int j0 = blockIdx.x * 128;
    const int tid = threadIdx.x;
    const int ty = tid >> 4, tx = tid & 15;

    __shared__ float As[16][128];
    __shared__ float ksT[64][136];   // [c][jl], jl in 0..133

    // load k_s rows [j0-3, j0+131) transposed
    {
        int jl = tid >> 4;             // 0..15
        int c  = (tid & 15) * 4;       // 0..60
        const float* kbase = g_ks + (size_t)b * L_ * D_ + h * DK_;
#pragma unroll
        for (int p = 0; p < 9; p++) {
            int j = jl + p * 16;
            if (j < 134) {
                int gj = j0 + j - PAD_;
                float4 kv = make_float4(0,0,0,0);
                if (gj >= 0 && gj < L_)
                    kv = *(const float4*)(kbase + (size_t)gj * D_ + c);
                ksT[c+0][j] = kv.x; ksT[c+1][j] = kv.y;
                ksT[c+2][j] = kv.z; ksT[c+3][j] = kv.w;
            }
        }
    }

    float acc[8][8];
#pragma unroll
    for (int i = 0; i < 8; i++)
#pragma unroll
        for (int j = 0; j < 8; j++) acc[i][j] = 0.f;

    const float* Abase = g_qcat + (size_t)z * L_ * NCAT;
    const int lr = tid >> 2, lc = (tid & 3) << 2;

    for (int k0 = 0; k0 < NCAT; k0 += 16) {
        __syncthreads();   // also covers ksT init on first iter
#pragma unroll
        for (int s = 0; s < 2; s++) {
            int row = lr + s * 64;
            float4 va = *(const float4*)(Abase + (size_t)(i0 + row) * NCAT + k0 + lc);
            As[lc+0][row] = va.x; As[lc+1][row] = va.y;
            As[lc+2][row] = va.z; As[lc+3][row] = va.w;
        }
        __syncthreads();
        const int t  = k0 >> 6;     // 0..6 (constant within a 16-chunk)
        const int c0 = k0 & 63;
#pragma unroll
        for (int kk = 0; kk < 16; kk++) {
            float ra[8], rb[8];
            *(float4*)(ra)   = *(const float4*)&As[kk][ty*8];
            *(float4*)(ra+4) = *(const float4*)&As[kk][ty*8+4];
            const float* brow = &ksT[c0 + kk][t + tx];
#pragma unroll
            for (int j = 0; j < 8; j++) rb[j] = brow[16*j];
#pragma unroll
            for (int i = 0; i < 8; i++)
#pragma unroll
                for (int j = 0; j < 8; j++)
                    acc[i][j] = fmaf(ra[i], rb[j], acc[i][j]);
        }
    }

    // epilogue: local cols = tx + 16*j
    float* out = attn + ((size_t)z * L_ + i0) * L_ + j0;
#pragma unroll
    for (int i = 0; i < 8; i++) {
        int gi = ty*8 + i;
        float rbv = g_rowbias[(size_t)z * L_ + i0 + gi];
        float* orow = out + (size_t)gi * L_;
#pragma unroll
        for (int j = 0; j < 8; j++)
            orow[tx + 16*j] = acc[i][j] * 0.125f + rbv;
    }
}

// ---------------------------------------------------------------------------
// Row softmax in-place on attn; applies mask; duplicates head 0 to one_head.
// one block (256 threads) per row of 1024.
// ---------------------------------------------------------------------------
__global__ __launch_bounds__(256) void softmax_kernel(
    float* __restrict__ attn, const unsigned char* __restrict__ mask,
    float* __restrict__ one_head)
{
    const int r = blockIdx.x;          // (b*8+h)*1024 + i
    const int i = r & (L_-1);
    const int bh = r >> 10;
    const int h = bh & (H_-1), b = bh >> 3;
    float* row = attn + (size_t)r * L_;
    const unsigned char* mrow = mask + ((size_t)(b*L_ + i)) * L_;
    const int t4 = threadIdx.x * 4;

    float4 v = *(const float4*)(row + t4);
    uchar4 m = *(const uchar4*)(mrow + t4);
    float x0 = m.x ? -INFINITY : v.x;
    float x1 = m.y ? -INFINITY : v.y;
    float x2 = m.z ? -INFINITY : v.z;
    float x3 = m.w ? -INFINITY : v.w;

    __shared__ float sm[8], ss[8];
    float mx = fmaxf(fmaxf(x0, x1), fmaxf(x2, x3));
#pragma unroll
    for (int o = 16; o; o >>= 1) mx = fmaxf(mx, __shfl_xor_sync(0xffffffffu, mx, o));
    if ((threadIdx.x & 31) == 0) sm[threadIdx.x >> 5] = mx;
    __syncthreads();
    if (threadIdx.x < 32) {
        float t = (threadIdx.x < 8) ? sm[threadIdx.x] : -INFINITY;
#pragma unroll
        for (int o = 4; o; o >>= 1) t = fmaxf(t, __shfl_xor_sync(0xffffffffu, t, o));
        if (threadIdx.x == 0) sm[0] = t;
    }
    __syncthreads();
    mx = sm[0];

    float e0 = __expf(x0 - mx), e1 = __expf(x1 - mx);
    float e2 = __expf(x2 - mx), e3 = __expf(x3 - mx);
    float s = (e0 + e1) + (e2 + e3);
#pragma unroll
    for (int o = 16; o; o >>= 1) s += __shfl_xor_sync(0xffffffffu, s, o);
    if ((threadIdx.x & 31) == 0) ss[threadIdx.x >> 5] = s;
    __syncthreads();
    if (threadIdx.x < 32) {
        float t = (threadIdx.x < 8) ? ss[threadIdx.x] : 0.f;
#pragma unroll
        for (int o = 4; o; o >>= 1) t += __shfl_xor_sync(0xffffffffu, t, o);
        if (threadIdx.x == 0) ss[0] = t;
    }
    __syncthreads();
    float inv = 1.0f / ss[0];

    float4 o = make_float4(e0*inv, e1*inv, e2*inv, e3*inv);
    *(float4*)(row + t4) = o;
    if (h == 0)
        *(float4*)(one_head + ((size_t)(b*L_ + i)) * L_ + t4) = o;
}

// ---------------------------------------------------------------------------
// ctx: per (b,h): C[1024,64] = attn[1024,1024] @ v_s_head[1024,64]
// writes into g_ctx laid out [B, L, D] (head = column slice). grid (1, 8, 64)
// ---------------------------------------------------------------------------
__global__ __launch_bounds__(256) void ctx_kernel(const float* __restrict__ attn)
{
    const int z = blockIdx.z;
    const int b = z >> 3, h = z & 7;
    const int bm = blockIdx.y * 128;
    const int tid = threadIdx.x;
    const int ty = tid >> 4, tx = tid & 15;

    __shared__ float As[16][128];
    __shared__ float Bs[16][64];

    const float* A  = attn + (size_t)z * L_ * L_;              // lda=1024
    const float* Vb = g_vs + (size_t)b * L_ * D_ + h * DK_;    // B[k][n]=Vb[k*512+n]

    float acc[8][4];
#pragma unroll
    for (int i = 0; i < 8; i++)
#pragma unroll
        for (int j = 0; j < 4; j++) acc[i][j] = 0.f;

    const int lr = tid >> 2, lc = (tid & 3) << 2;

    for (int k0 = 0; k0 < L_; k0 += 16) {
#pragma unroll
        for (int s = 0; s < 2; s++) {
            int row = lr + s * 64;
            float4 va = *(const float4*)(A + (size_t)(bm + row) * L_ + k0 + lc);
            As[lc+0][row] = va.x; As[lc+1][row] = va.y;
            As[lc+2][row] = va.z; As[lc+3][row] = va.w;
        }
        {
            int r  = tid >> 4;           // 0..15
            int cc = (tid & 15) << 2;    // 0..60
            float4 vb = *(const float4*)(Vb + (size_t)(k0 + r) * D_ + cc);
            *(float4*)&Bs[r][cc] = vb;
        }
        __syncthreads();
#pragma unroll
        for (int kk = 0; kk < 16; kk++) {
            float ra[8], rb[4];
            *(float4*)(ra)   = *(const float4*)&As[kk][ty*8];
            *(float4*)(ra+4) = *(const float4*)&As[kk][ty*8+4];
            *(float4*)(rb)   = *(const float4*)&Bs[kk][tx*4];
#pragma unroll
            for (int i = 0; i < 8; i++)
#pragma unroll
                for (int j = 0; j < 4; j++)
                    acc[i][j] = fmaf(ra[i], rb[j], acc[i][j]);
        }
        __syncthreads();
    }

    float* C = g_ctx + (size_t)b * L_ * D_ + h * DK_;
#pragma unroll
    for (int i = 0; i < 8; i++) {
        float4 o = make_float4(acc[i][0], acc[i][1], acc[i][2], acc[i][3]);
        *(float4*)(C + (size_t)(bm + ty*8 + i) * D_ + tx*4) = o;
    }
}

// ---------------------------------------------------------------------------
extern "C" void kernel_launch(void* const* d_in, const int* in_sizes, int n_in,
                              void* d_out, int out_size)
{
    const float* q      = (const float*)d_in[0];
    const float* k      = (const float*)d_in[1];
    const float* v      = (const float*)d_in[2];
    const unsigned char* mask = (const unsigned char*)d_in[3];
    const float* Wq     = (const float*)d_in[4];
    const float* bq     = (const float*)d_in[5];
    const float* Wk     = (const float*)d_in[6];
    const float* bk     = (const float*)d_in[7];
    const float* Wv     = (const float*)d_in[8];
    const float* bv     = (const float*)d_in[9];
    const float* Wker   = (const float*)d_in[10];
    const float* bker   = (const float*)d_in[11];
    const float* Wqb    = (const float*)d_in[12];
    const float* bqb    = (const float*)d_in[13];
    const float* bias_b = (const float*)d_in[14];
    const float* Wproj  = (const float*)d_in[15];
    const float* bproj  = (const float*)d_in[16];

    float* out      = (float*)d_out;
    float* attn     = out + (size_t)B_ * L_ * D_;
    float* one_head = attn + (size_t)B_ * H_ * L_ * L_;

    void* p;
    cudaGetSymbolAddress(&p, g_qs);  float* qs  = (float*)p;
    cudaGetSymbolAddress(&p, g_ks);  float* ks  = (float*)p;
    cudaGetSymbolAddress(&p, g_vs);  float* vs  = (float*)p;
    cudaGetSymbolAddress(&p, g_ctx); float* ctx = (float*)p;

    const int M = B_ * L_;  // 8192
    dim3 blk(256);

    // 1) projections -> q_s / k_s / v_s  ([B,L,D], head = col slice)
    sgemm_nt_kernel<<<dim3(D_/128, M/128), blk>>>(q, Wq, bq, qs, M, D_, D_);
    sgemm_nt_kernel<<<dim3(D_/128, M/128), blk>>>(k, Wk, bk, ks, M, D_, D_);
    sgemm_nt_kernel<<<dim3(D_/128, M/128), blk>>>(v, Wv, bv, vs, M, D_, D_);

    // 2) folded biases
    bcat_kernel<<<(H_*NCAT + 255)/256, 256>>>(bker);
    rowbias_kernel<<<(B_*H_*L_*32)/256, 256>>>(Wqb, bqb, bias_b);

    // 3) Qcat = q_s_head @ Wker_h + bcat
    qcat_kernel<<<dim3(4, L_/128, B_*H_), blk>>>(Wker);

    // 4) raw logits -> attn region
    logits_kernel<<<dim3(L_/128, L_/128, B_*H_), blk>>>(attn);

    // 5) softmax in place (+ one_head copy)
    softmax_kernel<<<B_*H_*L_, 256>>>(attn, mask, one_head);

    // 6) ctx = attn @ v_s   -> [B,L,D]
    ctx_kernel<<<dim3(1, L_/128, B_*H_), blk>>>(attn);

    // 7) out = ctx @ Wproj^T + bproj
    sgemm_nt_kernel<<<dim3(D_/128, M/128), blk>>>(ctx, Wproj, bproj, out, M, D_, D_);
}

// round 5
// speedup vs baseline: 1.6402x; 1.6402x over previous
#include <cuda_runtime.h>
#include <cuda_bf16.h>
#include <cstdint>

#define B_   8
#define L_   1024
#define D_   512
#define H_   8
#define DK_  64
#define KW_  7
#define PAD_ 3
#define NCAT 448   /* KW*DK */

// ---------------- scratch (device globals; no runtime allocation) ----------
__device__ float g_qs[B_*L_*D_];
__device__ float g_ks[B_*L_*D_];
__device__ float g_vs[B_*L_*D_];
__device__ float g_rowbias[B_*H_*L_];
__device__ float g_bcat[H_*NCAT];
__device__ float g_ctx[B_*L_*D_];
// bf16 hi/lo operands for the tensor-core logits GEMM
__device__ __align__(16) __nv_bfloat16 g_qcat_hi[(size_t)B_*H_*L_*NCAT];
__device__ __align__(16) __nv_bfloat16 g_qcat_lo[(size_t)B_*H_*L_*NCAT];
__device__ __align__(16) __nv_bfloat16 g_kcat_hi[(size_t)B_*H_*L_*NCAT];
__device__ __align__(16) __nv_bfloat16 g_kcat_lo[(size_t)B_*H_*L_*NCAT];

// ====================== baseline-PTX tensor helpers ========================
static __device__ __forceinline__ uint32_t smem_u32(const void* p){
    uint32_t a;
    asm("{ .reg .u64 t; cvta.to.shared.u64 t, %1; cvt.u32.u64 %0, t; }"
        : "=r"(a) : "l"(p));
    return a;
}
#define CP_ASYNC16(dst, src) \
    asm volatile("cp.async.cg.shared.global [%0], [%1], 16;" \
                 :: "r"(dst), "l"(src) : "memory")
#define CP_COMMIT() asm volatile("cp.async.commit_group;" ::: "memory")
#define CP_WAIT(n)  asm volatile("cp.async.wait_group %0;" :: "n"(n) : "memory")
#define LDSM4(r0, r1, r2, r3, addr) \
    asm volatile("ldmatrix.sync.aligned.m8n8.x4.shared.b16 {%0,%1,%2,%3}, [%4];" \
                 : "=r"(r0), "=r"(r1), "=r"(r2), "=r"(r3) : "r"(addr))
#define MMA16816(d, a, b) \
    asm volatile("mma.sync.aligned.m16n8k16.row.col.f32.bf16.bf16.f32 " \
                 "{%0,%1,%2,%3},{%4,%5,%6,%7},{%8,%9},{%0,%1,%2,%3};" \
                 : "+f"((d)[0]), "+f"((d)[1]), "+f"((d)[2]), "+f"((d)[3]) \
                 : "r"((a)[0]), "r"((a)[1]), "r"((a)[2]), "r"((a)[3]), \
                   "r"((b)[0]), "r"((b)[1]))

// bf16 split helpers
static __device__ __forceinline__ unsigned pk2(float a, float b){
    __nv_bfloat162 t = __floats2bfloat162_rn(a, b);
    return *reinterpret_cast<unsigned*>(&t);
}
static __device__ __forceinline__ float bhi(float x){
    return __bfloat162float(__float2bfloat16_rn(x));
}

// ---------------------------------------------------------------------------
// Generic 128x128 SGEMM, C[M,N] = A[M,K] @ W[N,K]^T + bias[N]
// ---------------------------------------------------------------------------
__global__ __launch_bounds__(256) void sgemm_nt_kernel(
    const float* __restrict__ A, const float* __restrict__ W,
    const float* __restrict__ bias, float* __restrict__ C,
    int M, int N, int K)
{
    __shared__ float As[16][128];
    __shared__ float Bs[16][128];
    const int bm = blockIdx.y * 128;
    const int bn = blockIdx.x * 128;
    const int tid = threadIdx.x;
    const int ty = tid >> 4, tx = tid & 15;
    const int lr = tid >> 2;
    const int lc = (tid & 3) << 2;

    float acc[8][8];
#pragma unroll
    for (int i = 0; i < 8; i++)
#pragma unroll
        for (int j = 0; j < 8; j++) acc[i][j] = 0.f;

    for (int k0 = 0; k0 < K; k0 += 16) {
#pragma unroll
        for (int s = 0; s < 2; s++) {
            int row = lr + s * 64;
            float4 va = *(const float4*)(A + (size_t)(bm + row) * K + k0 + lc);
            As[lc+0][row] = va.x; As[lc+1][row] = va.y;
            As[lc+2][row] = va.z; As[lc+3][row] = va.w;
            float4 vb = *(const float4*)(W + (size_t)(bn + row) * K + k0 + lc);
            Bs[lc+0][row] = vb.x; Bs[lc+1][row] = vb.y;
            Bs[lc+2][row] = vb.z; Bs[lc+3][row] = vb.w;
        }
        __syncthreads();
#pragma unroll
        for (int kk = 0; kk < 16; kk++) {
            float ra[8], rb[8];
            *(float4*)(ra)   = *(const float4*)&As[kk][ty*8];
            *(float4*)(ra+4) = *(const float4*)&As[kk][ty*8+4];
            *(float4*)(rb)   = *(const float4*)&Bs[kk][tx*4];
            *(float4*)(rb+4) = *(const float4*)&Bs[kk][64 + tx*4];
#pragma unroll
            for (int i = 0; i < 8; i++)
#pragma unroll
                for (int j = 0; j < 8; j++)
                    acc[i][j] = fmaf(ra[i], rb[j], acc[i][j]);
        }
        __syncthreads();
    }

    float4 b0 = *(const float4*)(bias + bn + tx*4);
    float4 b1 = *(const float4*)(bias + bn + 64 + tx*4);
#pragma unroll
    for (int i = 0; i < 8; i++) {
        size_t ro = (size_t)(bm + ty*8 + i) * N + bn;
        float4 o0 = make_float4(acc[i][0]+b0.x, acc[i][1]+b0.y,
                                acc[i][2]+b0.z, acc[i][3]+b0.w);
        float4 o1 = make_float4(acc[i][4]+b1.x, acc[i][5]+b1.y,
                                acc[i][6]+b1.z, acc[i][7]+b1.w);
        *(float4*)(C + ro + tx*4)      = o0;
        *(float4*)(C + ro + 64 + tx*4) = o1;
    }
}

// ---------------------------------------------------------------------------
// bcat[h, t*64+c] = bker[h,c,t]
// ---------------------------------------------------------------------------
__global__ void bcat_kernel(const float* __restrict__ bker)
{
    int n = blockIdx.x * blockDim.x + threadIdx.x;
    if (n >= H_ * NCAT) return;
    int h = n / NCAT, r = n % NCAT, t = r / DK_, c = r % DK_;
    g_bcat[n] = bker[(size_t)(h*DK_ + c) * KW_ + t];
}

// ---------------------------------------------------------------------------
// rowbias[b,h,i] = (q_s[b,h,i,:]·Wqb[h] + bqb[h] + bias_b[h]) / 8
// ---------------------------------------------------------------------------
__global__ void rowbias_kernel(const float* __restrict__ Wqb,
                               const float* __restrict__ bqb,
                               const float* __restrict__ bias_b)
{
    int warp = (blockIdx.x * blockDim.x + threadIdx.x) >> 5;
    int lane = threadIdx.x & 31;
    if (warp >= B_*H_*L_) return;
    int i = warp & (L_-1);
    int bh = warp >> 10;
    int h = bh & (H_-1), b = bh >> 3;
    const float* qrow = g_qs + ((size_t)(b*L_ + i)) * D_ + h*DK_;
    const float* w = Wqb + h*DK_;
    float s = qrow[lane]*w[lane] + qrow[lane+32]*w[lane+32];
#pragma unroll
    for (int o = 16; o; o >>= 1) s += __shfl_xor_sync(0xffffffffu, s, o);
    if (lane == 0)
        g_rowbias[warp] = (s + bqb[h] + bias_b[h]) * 0.125f;
}

// ---------------------------------------------------------------------------
// Qcat: per (b,h): Qcat[i, n=t*64+c] = sum_d q_s[i,d]*Wker[h,c,t,d] + bcat
// Writes bf16 hi/lo split. grid (4, 8, 64)
// ---------------------------------------------------------------------------
__global__ __launch_bounds__(256) void qcat_kernel(const float* __restrict__ Wker)
{
    const int z = blockIdx.z;
    const int b = z >> 3, h = z & 7;
    const int bm = blockIdx.y * 128;
    const int bn = blockIdx.x * 128;
    const int tid = threadIdx.x;
    const int ty = tid >> 4, tx = tid & 15;

    __shared__ float As[16][128];
    __shared__ float Bs[16][128];

    const float* A = g_qs + (size_t)b * L_ * D_ + h * DK_;
    const float* W = Wker + (size_t)h * DK_ * NCAT;

    float acc[8][8];
#pragma unroll
    for (int i = 0; i < 8; i++)
#pragma unroll
        for (int j = 0; j < 8; j++) acc[i][j] = 0.f;

    const int lr = tid >> 2, lc = (tid & 3) << 2;

    for (int k0 = 0; k0 < DK_; k0 += 16) {
#pragma unroll
        for (int s = 0; s < 2; s++) {
            int row = lr + s * 64;
            float4 va = *(const float4*)(A + (size_t)(bm + row) * D_ + k0 + lc);
            As[lc+0][row] = va.x; As[lc+1][row] = va.y;
            As[lc+2][row] = va.z; As[lc+3][row] = va.w;
        }
        for (int idx = tid; idx < 512; idx += 256) {
            int nloc = idx >> 2;
            int kl   = (idx & 3) << 2;
            int gn = bn + nloc;
            float4 vb = make_float4(0,0,0,0);
            if (gn < NCAT) {
                int t = gn >> 6, c = gn & 63;
                vb = *(const float4*)(W + (size_t)c * NCAT + t * DK_ + k0 + kl);
            }
            Bs[kl+0][nloc] = vb.x; Bs[kl+1][nloc] = vb.y;
            Bs[kl+2][nloc] = vb.z; Bs[kl+3][nloc] = vb.w;
        }
        __syncthreads();
#pragma unroll
        for (int kk = 0; kk < 16; kk++) {
            float ra[8], rb[8];
            *(float4*)(ra)   = *(const float4*)&As[kk][ty*8];
            *(float4*)(ra+4) = *(const float4*)&As[kk][ty*8+4];
            *(float4*)(rb)   = *(const float4*)&Bs[kk][tx*4];
            *(float4*)(rb+4) = *(const float4*)&Bs[kk][64 + tx*4];
#pragma unroll
            for (int i = 0; i < 8; i++)
#pragma unroll
                for (int j = 0; j < 8; j++)
                    acc[i][j] = fmaf(ra[i], rb[j], acc[i][j]);
        }
        __syncthreads();
    }

    __nv_bfloat16* Ch = g_qcat_hi + (size_t)z * L_ * NCAT;
    __nv_bfloat16* Cl = g_qcat_lo + (size_t)z * L_ * NCAT;
    int c0g = bn + tx*4, c1g = bn + 64 + tx*4;
    float4 b0 = make_float4(0,0,0,0), b1 = make_float4(0,0,0,0);
    if (c0g < NCAT) b0 = *(const float4*)(g_bcat + h*NCAT + c0g);
    if (c1g < NCAT) b1 = *(const float4*)(g_bcat + h*NCAT + c1g);
#pragma unroll
    for (int i = 0; i < 8; i++) {
        size_t ro = (size_t)(bm + ty*8 + i) * NCAT;
        if (c0g < NCAT) {
            float v0 = acc[i][0]+b0.x, v1 = acc[i][1]+b0.y;
            float v2 = acc[i][2]+b0.z, v3 = acc[i][3]+b0.w;
            float h0 = bhi(v0), h1 = bhi(v1), h2 = bhi(v2), h3 = bhi(v3);
            uint2 whi = make_uint2(pk2(h0,h1), pk2(h2,h3));
            uint2 wlo = make_uint2(pk2(v0-h0,v1-h1), pk2(v2-h2,v3-h3));
            *(uint2*)(Ch + ro + c0g) = whi;
            *(uint2*)(Cl + ro + c0g) = wlo;
        }
        if (c1g < NCAT) {
            float v0 = acc[i][4]+b1.x, v1 = acc[i][5]+b1.y;
            float v2 = acc[i][6]+b1.z, v3 = acc[i][7]+b1.w;
            float h0 = bhi(v0), h1 = bhi(v1), h2 = bhi(v2), h3 = bhi(v3);
            uint2 whi = make_uint2(pk2(h0,h1), pk2(h2,h3));
            uint2 wlo = make_uint2(pk2(v0-h0,v1-h1), pk2(v2-h2,v3-h3));
            *(uint2*)(Ch + ro + c1g) = whi;
            *(uint2*)(Cl + ro + c1g) = wlo;
        }
    }
}

// ---------------------------------------------------------------------------
// Kcat prep: Kcat[z][j][t*64+c] = k_s[b][j+t-3][h*64+c]  (0 outside range)
// split into bf16 hi/lo.
// ---------------------------------------------------------------------------
__global__ __launch_bounds__(256) void kcat_prep_kernel()
{
    int idx = blockIdx.x * 256 + threadIdx.x;
    if (idx >= B_*H_*L_*(NCAT/8)) return;
    int c8 = idx % (NCAT/8);
    int rest = idx / (NCAT/8);
    int j = rest & (L_-1);
    int z = rest >> 10;
    int b = z >> 3, h = z & 7;
    int cpos = c8 * 8;
    int t = cpos >> 6, cc = cpos & 63;
    int src = j + t - PAD_;
    float4 v0 = make_float4(0,0,0,0), v1 = make_float4(0,0,0,0);
    if (src >= 0 && src < L_) {
        const float* p = g_ks + ((size_t)(b*L_ + src)) * D_ + h*DK_ + cc;
        v0 = *(const float4*)p;
        v1 = *(const float4*)(p + 4);
    }
    float f[8] = {v0.x, v0.y, v0.z, v0.w, v1.x, v1.y, v1.z, v1.w};
    float hh[8], ll[8];
#pragma unroll
    for (int i = 0; i < 8; i++) { hh[i] = bhi(f[i]); ll[i] = f[i] - hh[i]; }
    uint4 whi = make_uint4(pk2(hh[0],hh[1]), pk2(hh[2],hh[3]),
                           pk2(hh[4],hh[5]), pk2(hh[6],hh[7]));
    uint4 wlo = make_uint4(pk2(ll[0],ll[1]), pk2(ll[2],ll[3]),
                           pk2(ll[4],ll[5]), pk2(ll[6],ll[7]));
    size_t off = (size_t)z * L_ * NCAT + (size_t)j * NCAT + cpos;
    *(uint4*)(g_kcat_hi + off) = whi;
    *(uint4*)(g_kcat_lo + off) = wlo;
}

// ---------------------------------------------------------------------------
// Tensor-core logits via mma.sync (baseline PTX, works on compute_103):
// per CTA: S[128,128] tile, K=448 in 14 chunks of 32.
// D = Qh·Kh + Qh·Kl + Ql·Kh  (bf16x3, fp32 accumulate).
// smem row layout: 128 rows x 128B; chunks 0-3 = hi k-cols, 4-7 = lo;
// chunk position XOR-swizzled by (row&7) -> conflict-free ldmatrix.
// 8 warps as 2(m) x 4(n); warp tile 64x32. grid (8, 8, 64).
// ---------------------------------------------------------------------------
#define LOG_STAGE 32768
#define LOG_SMEM  (2*LOG_STAGE)

__global__ __launch_bounds__(256, 1) void logits_mma_kernel(float* __restrict__ attn)
{
    extern __shared__ char smem[];
    const uint32_t sbase = smem_u32(smem);

    const int tid  = threadIdx.x;
    const int wid  = tid >> 5, lane = tid & 31;
    const int wm   = wid >> 2, wn = wid & 3;

    const int z  = blockIdx.z;
    const int i0 = blockIdx.y * 128;
    const int j0 = blockIdx.x * 128;

    const __nv_bfloat16* qh = g_qcat_hi + (size_t)z * L_ * NCAT + (size_t)i0 * NCAT;
    const __nv_bfloat16* ql = g_qcat_lo + (size_t)z * L_ * NCAT + (size_t)i0 * NCAT;
    const __nv_bfloat16* kh = g_kcat_hi + (size_t)z * L_ * NCAT + (size_t)j0 * NCAT;
    const __nv_bfloat16* kl = g_kcat_lo + (size_t)z * L_ * NCAT + (size_t)j0 * NCAT;

    // issue cp.async fills for stage s, K-chunk c (32 bf16 cols)
    auto issue = [&](int s, int c) {
        const uint32_t sb = sbase + s * LOG_STAGE;
#pragma unroll
        for (int q = 0; q < 4; q++) {          // A: 1024 16B chunks
            int u  = q * 256 + tid;
            int r  = u >> 3, cj = u & 7;
            const __nv_bfloat16* src =
                (cj < 4 ? qh : ql) + (size_t)r * NCAT + c * 32 + (cj & 3) * 8;
            uint32_t dst = sb + r * 128 + 16 * (cj ^ (r & 7));
            CP_ASYNC16(dst, src);
        }
#pragma unroll
        for (int q = 0; q < 4; q++) {          // B
            int u  = q * 256 + tid;
            int r  = u >> 3, cj = u & 7;
            const __nv_bfloat16* src =
                (cj < 4 ? kh : kl) + (size_t)r * NCAT + c * 32 + (cj & 3) * 8;
            uint32_t dst = sb + 16384 + r * 128 + 16 * (cj ^ (r & 7));
            CP_ASYNC16(dst, src);
        }
    };

    float acc[4][4][4];
#pragma unroll
    for (int i = 0; i < 4; i++)
#pragma unroll
        for (int j = 0; j < 4; j++)
#pragma unroll
            for (int e = 0; e < 4; e++) acc[i][j][e] = 0.f;

    issue(0, 0);
    CP_COMMIT();

    const int lrow = (lane & 7) + 8 * ((lane >> 3) & 1);  // ldmatrix row within 16
    const int lchk = lane >> 4;                           // ldmatrix k-chunk sel

    for (int c = 0; c < 14; c++) {
        const int s = c & 1;
        if (c + 1 < 14) { issue(s ^ 1, c + 1); CP_COMMIT(); CP_WAIT(1); }
        else            { CP_WAIT(0); }
        __syncthreads();

        const uint32_t sA = sbase + s * LOG_STAGE;
        const uint32_t sB = sA + 16384;

#pragma unroll
        for (int ks = 0; ks < 2; ks++) {
            // ---- B fragments: 2 groups of n16, hi + lo ----
            uint32_t bh[4][2], bl[4][2];
#pragma unroll
            for (int g = 0; g < 2; g++) {
                int r  = wn * 32 + g * 16 + lrow;
                int ch = ks * 2 + lchk;
                uint32_t ah_ = sB + r * 128 + 16 * ((ch)     ^ (r & 7));
                uint32_t al_ = sB + r * 128 + 16 * ((ch + 4) ^ (r & 7));
                uint32_t r0, r1, r2, r3;
                LDSM4(r0, r1, r2, r3, ah_);
                bh[2*g][0] = r0; bh[2*g][1] = r2;
                bh[2*g+1][0] = r1; bh[2*g+1][1] = r3;
                LDSM4(r0, r1, r2, r3, al_);
                bl[2*g][0] = r0; bl[2*g][1] = r2;
                bl[2*g+1][0] = r1; bl[2*g+1][1] = r3;
            }
            // ---- A fragments + MMAs ----
#pragma unroll
            for (int mf = 0; mf < 4; mf++) {
                int r  = wm * 64 + mf * 16 + lrow;
                int ch = ks * 2 + lchk;
                uint32_t ah[4], al[4];
                LDSM4(ah[0], ah[1], ah[2], ah[3],
                      sA + r * 128 + 16 * ((ch)     ^ (r & 7)));
                LDSM4(al[0], al[1], al[2], al[3],
                      sA + r * 128 + 16 * ((ch + 4) ^ (r & 7)));
#pragma unroll
                for (int nf = 0; nf < 4; nf++) {
                    MMA16816(acc[mf][nf], ah, bh[nf]);
                    MMA16816(acc[mf][nf], ah, bl[nf]);
                    MMA16816(acc[mf][nf], al, bh[nf]);
                }
            }
        }
        __syncthreads();
    }

    // ---- epilogue: c0,c1 -> row lane>>2; c2,c3 -> row (lane>>2)+8 ----
    const int rbase = i0 + wm * 64 + (lane >> 2);
    const int cbase = j0 + wn * 32 + 2 * (lane & 3);
#pragma unroll
    for (int mf = 0; mf < 4; mf++) {
        int gi0 = rbase + mf * 16;
        float rb0 = g_rowbias[(size_t)z * L_ + gi0];
        float rb1 = g_rowbias[(size_t)z * L_ + gi0 + 8];
        float* row0 = attn + ((size_t)z * L_ + gi0) * L_;
        float* row1 = row0 + 8 * L_;
#pragma unroll
        for (int nf = 0; nf < 4; nf++) {
            int gj = cbase + nf * 8;
            float2 o0 = make_float2(acc[mf][nf][0]*0.125f + rb0,
                                    acc[mf][nf][1]*0.125f + rb0);
            float2 o1 = make_float2(acc[mf][nf][2]*0.125f + rb1,
                                    acc[mf][nf][3]*0.125f + rb1);
            *(float2*)(row0 + gj) = o0;
            *(float2*)(row1 + gj) = o1;
        }
    }
}

// ---------------------------------------------------------------------------
// Row softmax in-place on attn; mask; head-0 duplicate.
// ---------------------------------------------------------------------------
__global__ __launch_bounds__(256) void softmax_kernel(
    float* __restrict__ attn, const unsigned char* __restrict__ mask,
    float* __restrict__ one_head)
{
    const int r = blockIdx.x;
    const int i = r & (L_-1);
    const int bh = r >> 10;
    const int h = bh & (H_-1), b = bh >> 3;
    float* row = attn + (size_t)r * L_;
    const unsigned char* mrow = mask + ((size_t)(b*L_ + i)) * L_;
    const int t4 = threadIdx.x * 4;

    float4 v = *(const float4*)(row + t4);
    uchar4 m = *(const uchar4*)(mrow + t4);
    float x0 = m.x ? -INFINITY : v.x;
    float x1 = m.y ? -INFINITY : v.y;
    float x2 = m.z ? -INFINITY : v.z;
    float x3 = m.w ? -INFINITY : v.w;

    __shared__ float sm[8], ss[8];
    float mx = fmaxf(fmaxf(x0, x1), fmaxf(x2, x3));
#pragma unroll
    for (int o = 16; o; o >>= 1) mx = fmaxf(mx, __shfl_xor_sync(0xffffffffu, mx, o));
    if ((threadIdx.x & 31) == 0) sm[threadIdx.x >> 5] = mx;
    __syncthreads();
    if (threadIdx.x < 32) {
        float t = (threadIdx.x < 8) ? sm[threadIdx.x] : -INFINITY;
#pragma unroll
        for (int o = 4; o; o >>= 1) t = fmaxf(t, __shfl_xor_sync(0xffffffffu, t, o));
        if (threadIdx.x == 0) sm[0] = t;
    }
    __syncthreads();
    mx = sm[0];

    float e0 = __expf(x0 - mx), e1 = __expf(x1 - mx);
    float e2 = __expf(x2 - mx), e3 = __expf(x3 - mx);
    float s = (e0 + e1) + (e2 + e3);
#pragma unroll
    for (int o = 16; o; o >>= 1) s += __shfl_xor_sync(0xffffffffu, s, o);
    if ((threadIdx.x & 31) == 0) ss[threadIdx.x >> 5] = s;
    __syncthreads();
    if (threadIdx.x < 32) {
        float t = (threadIdx.x < 8) ? ss[threadIdx.x] : 0.f;
#pragma unroll
        for (int o = 4; o; o >>= 1) t += __shfl_xor_sync(0xffffffffu, t, o);
        if (threadIdx.x == 0) ss[0] = t;
    }
    __syncthreads();
    float inv = 1.0f / ss[0];

    float4 o = make_float4(e0*inv, e1*inv, e2*inv, e3*inv);
    *(float4*)(row + t4) = o;
    if (h == 0)
        *(float4*)(one_head + ((size_t)(b*L_ + i)) * L_ + t4) = o;
}

// ---------------------------------------------------------------------------
// ctx: per (b,h): C[1024,64] = attn[1024,1024] @ v_s_head[1024,64]
// ---------------------------------------------------------------------------
__global__ __launch_bounds__(256) void ctx_kernel(const float* __restrict__ attn)
{
    const int z = blockIdx.z;
    const int b = z >> 3, h = z & 7;
    const int bm = blockIdx.y * 128;
    const int tid = threadIdx.x;
    const int ty = tid >> 4, tx = tid & 15;

    __shared__ float As[16][128];
    __shared__ float Bs[16][64];

    const float* A  = attn + (size_t)z * L_ * L_;
    const float* Vb = g_vs + (size_t)b * L_ * D_ + h * DK_;

    float acc[8][4];
#pragma unroll
    for (int i = 0; i < 8; i++)
#pragma unroll
        for (int j = 0; j < 4; j++) acc[i][j] = 0.f;

    const int lr = tid >> 2, lc = (tid & 3) << 2;

    for (int k0 = 0; k0 < L_; k0 += 16) {
#pragma unroll
        for (int s = 0; s < 2; s++) {
            int row = lr + s * 64;
            float4 va = *(const float4*)(A + (size_t)(bm + row) * L_ + k0 + lc);
            As[lc+0][row] = va.x; As[lc+1][row] = va.y;
            As[lc+2][row] = va.z; As[lc+3][row] = va.w;
        }
        {
            int r  = tid >> 4;
            int cc = (tid & 15) << 2;
            float4 vb = *(const float4*)(Vb + (size_t)(k0 + r) * D_ + cc);
            *(float4*)&Bs[r][cc] = vb;
        }
        __syncthreads();
#pragma unroll
        for (int kk = 0; kk < 16; kk++) {
            float ra[8], rb[4];
            *(float4*)(ra)   = *(const float4*)&As[kk][ty*8];
            *(float4*)(ra+4) = *(const float4*)&As[kk][ty*8+4];
            *(float4*)(rb)   = *(const float4*)&Bs[kk][tx*4];
#pragma unroll
            for (int i = 0; i < 8; i++)
#pragma unroll
                for (int j = 0; j < 4; j++)
                    acc[i][j] = fmaf(ra[i], rb[j], acc[i][j]);
        }
        __syncthreads();
    }

    float* C = g_ctx + (size_t)b * L_ * D_ + h * DK_;
#pragma unroll
    for (int i = 0; i < 8; i++) {
        float4 o = make_float4(acc[i][0], acc[i][1], acc[i][2], acc[i][3]);
        *(float4*)(C + (size_t)(bm + ty*8 + i) * D_ + tx*4) = o;
    }
}

// ---------------------------------------------------------------------------
extern "C" void kernel_launch(void* const* d_in, const int* in_sizes, int n_in,
                              void* d_out, int out_size)
{
    const float* q      = (const float*)d_in[0];
    const float* k      = (const float*)d_in[1];
    const float* v      = (const float*)d_in[2];
    const unsigned char* mask = (const unsigned char*)d_in[3];
    const float* Wq     = (const float*)d_in[4];
    const float* bq     = (const float*)d_in[5];
    const float* Wk     = (const float*)d_in[6];
    const float* bk     = (const float*)d_in[7];
    const float* Wv     = (const float*)d_in[8];
    const float* bv     = (const float*)d_in[9];
    const float* Wker   = (const float*)d_in[10];
    const float* bker   = (const float*)d_in[11];
    const float* Wqb    = (const float*)d_in[12];
    const float* bqb    = (const float*)d_in[13];
    const float* bias_b = (const float*)d_in[14];
    const float* Wproj  = (const float*)d_in[15];
    const float* bproj  = (const float*)d_in[16];

    float* out      = (float*)d_out;
    float* attn     = out + (size_t)B_ * L_ * D_;
    float* one_head = attn + (size_t)B_ * H_ * L_ * L_;

    void* p;
    cudaGetSymbolAddress(&p, g_qs);  float* qs  = (float*)p;
    cudaGetSymbolAddress(&p, g_ks);  float* ks  = (float*)p;
    cudaGetSymbolAddress(&p, g_vs);  float* vs  = (float*)p;
    cudaGetSymbolAddress(&p, g_ctx); float* ctx = (float*)p;

    static bool attr_done = false;
    if (!attr_done) {
        cudaFuncSetAttribute(logits_mma_kernel,
                             cudaFuncAttributeMaxDynamicSharedMemorySize,
                             LOG_SMEM);
        attr_done = true;
    }

    const int M = B_ * L_;  // 8192
    dim3 blk(256);

    // 1) projections
    sgemm_nt_kernel<<<dim3(D_/128, M/128), blk>>>(q, Wq, bq, qs, M, D_, D_);
    sgemm_nt_kernel<<<dim3(D_/128, M/128), blk>>>(k, Wk, bk, ks, M, D_, D_);
    sgemm_nt_kernel<<<dim3(D_/128, M/128), blk>>>(v, Wv, bv, vs, M, D_, D_);

    // 2) folded biases
    bcat_kernel<<<(H_*NCAT + 255)/256, 256>>>(bker);
    rowbias_kernel<<<(B_*H_*L_*32)/256, 256>>>(Wqb, bqb, bias_b);

    // 3) operand prep (bf16 hi/lo)
    qcat_kernel<<<dim3(4, L_/128, B_*H_), blk>>>(Wker);
    kcat_prep_kernel<<<(B_*H_*L_*(NCAT/8) + 255)/256, 256>>>();

    // 4) tensor-core logits -> attn region (raw, scaled + rowbias)
    logits_mma_kernel<<<dim3(L_/128, L_/128, B_*H_), 256, LOG_SMEM>>>(attn);

    // 5) softmax in place (+ one_head copy)
    softmax_kernel<<<B_*H_*L_, 256>>>(attn, mask, one_head);

    // 6) ctx = attn @ v_s
    ctx_kernel<<<dim3(1, L_/128, B_*H_), blk>>>(attn);

    // 7) out = ctx @ Wproj^T + bproj
    sgemm_nt_kernel<<<dim3(D_/128, M/128), blk>>>(ctx, Wproj, bproj, out, M, D_, D_);
}

// round 6
// speedup vs baseline: 2.1698x; 1.3229x over previous
#include <cuda_runtime.h>
#include <cuda_bf16.h>
#include <cstdint>

#define B_   8
#define L_   1024
#define D_   512
#define H_   8
#define DK_  64
#define KW_  7
#define PAD_ 3
#define NCAT 448   /* KW*DK */

// ---------------- scratch (device globals; no runtime allocation) ----------
__device__ float g_qs[B_*L_*D_];
__device__ float g_ks[B_*L_*D_];
__device__ float g_vs[B_*L_*D_];
__device__ float g_rowbias[B_*H_*L_];
__device__ float g_bcat[H_*NCAT];
// bf16 hi/lo operands
__device__ __align__(16) __nv_bfloat16 g_qcat_hi[(size_t)B_*H_*L_*NCAT];
__device__ __align__(16) __nv_bfloat16 g_qcat_lo[(size_t)B_*H_*L_*NCAT];
__device__ __align__(16) __nv_bfloat16 g_kcat_hi[(size_t)B_*H_*L_*NCAT];
__device__ __align__(16) __nv_bfloat16 g_kcat_lo[(size_t)B_*H_*L_*NCAT];
// projection inputs (bf16 split)
__device__ __align__(16) __nv_bfloat16 g_inq_hi[B_*L_*D_];
__device__ __align__(16) __nv_bfloat16 g_inq_lo[B_*L_*D_];
__device__ __align__(16) __nv_bfloat16 g_ink_hi[B_*L_*D_];
__device__ __align__(16) __nv_bfloat16 g_ink_lo[B_*L_*D_];
__device__ __align__(16) __nv_bfloat16 g_inv_hi[B_*L_*D_];
__device__ __align__(16) __nv_bfloat16 g_inv_lo[B_*L_*D_];
// weights (bf16 split): slots 0=Wq 1=Wk 2=Wv 3=Wproj
__device__ __align__(16) __nv_bfloat16 g_w_hi[4*D_*D_];
__device__ __align__(16) __nv_bfloat16 g_w_lo[4*D_*D_];
// v transposed per head: [z=(b*8+h)][n=0..63][k=0..1023]
__device__ __align__(16) __nv_bfloat16 g_vt_hi[(size_t)B_*H_*DK_*L_];
__device__ __align__(16) __nv_bfloat16 g_vt_lo[(size_t)B_*H_*DK_*L_];
// ctx in bf16 split, layout [B*L, 512]
__device__ __align__(16) __nv_bfloat16 g_ctx_hi[B_*L_*D_];
__device__ __align__(16) __nv_bfloat16 g_ctx_lo[B_*L_*D_];

// ====================== baseline-PTX tensor helpers ========================
static __device__ __forceinline__ uint32_t smem_u32(const void* p){
    uint32_t a;
    asm("{ .reg .u64 t; cvta.to.shared.u64 t, %1; cvt.u32.u64 %0, t; }"
        : "=r"(a) : "l"(p));
    return a;
}
#define CP_ASYNC16(dst, src) \
    asm volatile("cp.async.cg.shared.global [%0], [%1], 16;" \
                 :: "r"(dst), "l"(src) : "memory")
#define CP_COMMIT() asm volatile("cp.async.commit_group;" ::: "memory")
#define CP_WAIT(n)  asm volatile("cp.async.wait_group %0;" :: "n"(n) : "memory")
#define LDSM4(r0, r1, r2, r3, addr) \
    asm volatile("ldmatrix.sync.aligned.m8n8.x4.shared.b16 {%0,%1,%2,%3}, [%4];" \
                 : "=r"(r0), "=r"(r1), "=r"(r2), "=r"(r3) : "r"(addr))
#define MMA16816(d, a, b) \
    asm volatile("mma.sync.aligned.m16n8k16.row.col.f32.bf16.bf16.f32 " \
                 "{%0,%1,%2,%3},{%4,%5,%6,%7},{%8,%9},{%0,%1,%2,%3};" \
                 : "+f"((d)[0]), "+f"((d)[1]), "+f"((d)[2]), "+f"((d)[3]) \
                 : "r"((a)[0]), "r"((a)[1]), "r"((a)[2]), "r"((a)[3]), \
                   "r"((b)[0]), "r"((b)[1]))

static __device__ __forceinline__ unsigned pk2(float a, float b){
    __nv_bfloat162 t = __floats2bfloat162_rn(a, b);
    return *reinterpret_cast<unsigned*>(&t);
}
static __device__ __forceinline__ float bhi(float x){
    return __bfloat162float(__float2bfloat16_rn(x));
}

// ---------------------------------------------------------------------------
// conv_split: fp32 -> bf16 hi/lo.  n must be multiple of 8.
// ---------------------------------------------------------------------------
__global__ __launch_bounds__(256) void conv_split_kernel(
    const float* __restrict__ src, __nv_bfloat16* __restrict__ dh,
    __nv_bfloat16* __restrict__ dl, int n8)
{
    int i = blockIdx.x * 256 + threadIdx.x;
    if (i >= n8) return;
    const float4* s = (const float4*)(src + (size_t)i * 8);
    float4 v0 = s[0], v1 = s[1];
    float f[8] = {v0.x, v0.y, v0.z, v0.w, v1.x, v1.y, v1.z, v1.w};
    float hh[8], ll[8];
#pragma unroll
    for (int e = 0; e < 8; e++) { hh[e] = bhi(f[e]); ll[e] = f[e] - hh[e]; }
    uint4 whi = make_uint4(pk2(hh[0],hh[1]), pk2(hh[2],hh[3]),
                           pk2(hh[4],hh[5]), pk2(hh[6],hh[7]));
    uint4 wlo = make_uint4(pk2(ll[0],ll[1]), pk2(ll[2],ll[3]),
                           pk2(ll[4],ll[5]), pk2(ll[6],ll[7]));
    *(uint4*)(dh + (size_t)i * 8) = whi;
    *(uint4*)(dl + (size_t)i * 8) = wlo;
}

// ---------------------------------------------------------------------------
// Generic bf16x3 mma GEMM: C[M,N] = Ah@Bh^T + Ah@Bl^T + Al@Bh^T + bias[N]
// A [M,K] row-major bf16 hi/lo; B [N,K] row-major bf16 hi/lo; C fp32.
// Tile 128x128, 8 warps 2x4, K in chunks of 32 (kc = K/32), 2-stage cp.async.
// grid (N/128, M/128), 256 threads, 64KB dynamic smem.
// ---------------------------------------------------------------------------
#define GM_STAGE 32768
#define GM_SMEM  (2*GM_STAGE)

__global__ __launch_bounds__(256, 1) void gemm_mma_nt(
    const __nv_bfloat16* __restrict__ Ah, const __nv_bfloat16* __restrict__ Al,
    const __nv_bfloat16* __restrict__ Bh, const __nv_bfloat16* __restrict__ Bl,
    const float* __restrict__ bias, float* __restrict__ C, int K, int N)
{
    extern __shared__ char smem[];
    const uint32_t sbase = smem_u32(smem);
    const int kc = K >> 5;

    const int tid  = threadIdx.x;
    const int wid  = tid >> 5, lane = tid & 31;
    const int wm   = wid >> 2, wn = wid & 3;

    const int i0 = blockIdx.y * 128;
    const int j0 = blockIdx.x * 128;

    const __nv_bfloat16* ah = Ah + (size_t)i0 * K;
    const __nv_bfloat16* al = Al + (size_t)i0 * K;
    const __nv_bfloat16* bh_ = Bh + (size_t)j0 * K;
    const __nv_bfloat16* bl_ = Bl + (size_t)j0 * K;

    auto issue = [&](int s, int c) {
        const uint32_t sb = sbase + s * GM_STAGE;
#pragma unroll
        for (int q = 0; q < 4; q++) {
            int u  = q * 256 + tid;
            int r  = u >> 3, cj = u & 7;
            const __nv_bfloat16* src =
                (cj < 4 ? ah : al) + (size_t)r * K + c * 32 + (cj & 3) * 8;
            CP_ASYNC16(sb + r * 128 + 16 * (cj ^ (r & 7)), src);
        }
#pragma unroll
        for (int q = 0; q < 4; q++) {
            int u  = q * 256 + tid;
            int r  = u >> 3, cj = u & 7;
            const __nv_bfloat16* src =
                (cj < 4 ? bh_ : bl_) + (size_t)r * K + c * 32 + (cj & 3) * 8;
            CP_ASYNC16(sb + 16384 + r * 128 + 16 * (cj ^ (r & 7)), src);
        }
    };

    float acc[4][4][4];
#pragma unroll
    for (int i = 0; i < 4; i++)
#pragma unroll
        for (int j = 0; j < 4; j++)
#pragma unroll
            for (int e = 0; e < 4; e++) acc[i][j][e] = 0.f;

    issue(0, 0);
    CP_COMMIT();

    const int lrow = (lane & 7) + 8 * ((lane >> 3) & 1);
    const int lchk = lane >> 4;

    for (int c = 0; c < kc; c++) {
        const int s = c & 1;
        if (c + 1 < kc) { issue(s ^ 1, c + 1); CP_COMMIT(); CP_WAIT(1); }
        else            { CP_WAIT(0); }
        __syncthreads();

        const uint32_t sA = sbase + s * GM_STAGE;
        const uint32_t sB = sA + 16384;

#pragma unroll
        for (int ks = 0; ks < 2; ks++) {
            uint32_t bh[4][2], bl[4][2];
#pragma unroll
            for (int g = 0; g < 2; g++) {
                int r  = wn * 32 + g * 16 + lrow;
                int ch = ks * 2 + lchk;
                uint32_t r0, r1, r2, r3;
                LDSM4(r0, r1, r2, r3, sB + r * 128 + 16 * ((ch)     ^ (r & 7)));
                bh[2*g][0] = r0; bh[2*g][1] = r2;
                bh[2*g+1][0] = r1; bh[2*g+1][1] = r3;
                LDSM4(r0, r1, r2, r3, sB + r * 128 + 16 * ((ch + 4) ^ (r & 7)));
                bl[2*g][0] = r0; bl[2*g][1] = r2;
                bl[2*g+1][0] = r1; bl[2*g+1][1] = r3;
            }
#pragma unroll
            for (int mf = 0; mf < 4; mf++) {
                int r  = wm * 64 + mf * 16 + lrow;
                int ch = ks * 2 + lchk;
                uint32_t ah_[4], al_[4];
                LDSM4(ah_[0], ah_[1], ah_[2], ah_[3],
                      sA + r * 128 + 16 * ((ch)     ^ (r & 7)));
                LDSM4(al_[0], al_[1], al_[2], al_[3],
                      sA + r * 128 + 16 * ((ch + 4) ^ (r & 7)));
#pragma unroll
                for (int nf = 0; nf < 4; nf++) {
                    MMA16816(acc[mf][nf], ah_, bh[nf]);
                    MMA16816(acc[mf][nf], ah_, bl[nf]);
                    MMA16816(acc[mf][nf], al_, bh[nf]);
                }
            }
        }
        __syncthreads();
    }

    const int rbase = i0 + wm * 64 + (lane >> 2);
    const int cbase = j0 + wn * 32 + 2 * (lane & 3);
#pragma unroll
    for (int mf = 0; mf < 4; mf++) {
        int gi = rbase + mf * 16;
        float* row0 = C + (size_t)gi * N;
        float* row1 = row0 + 8 * N;
#pragma unroll
        for (int nf = 0; nf < 4; nf++) {
            int gj = cbase + nf * 8;
            float b0 = bias[gj], b1 = bias[gj + 1];
            *(float2*)(row0 + gj) = make_float2(acc[mf][nf][0] + b0,
                                                acc[mf][nf][1] + b1);
            *(float2*)(row1 + gj) = make_float2(acc[mf][nf][2] + b0,
                                                acc[mf][nf][3] + b1);
        }
    }
}

// ---------------------------------------------------------------------------
// bcat[h, t*64+c] = bker[h,c,t]
// ---------------------------------------------------------------------------
__global__ void bcat_kernel(const float* __restrict__ bker)
{
    int n = blockIdx.x * blockDim.x + threadIdx.x;
    if (n >= H_ * NCAT) return;
    int h = n / NCAT, r = n % NCAT, t = r / DK_, c = r % DK_;
    g_bcat[n] = bker[(size_t)(h*DK_ + c) * KW_ + t];
}

// ---------------------------------------------------------------------------
// rowbias[b,h,i] = (q_s[b,h,i,:]·Wqb[h] + bqb[h] + bias_b[h]) / 8
// ---------------------------------------------------------------------------
__global__ void rowbias_kernel(const float* __restrict__ Wqb,
                               const float* __restrict__ bqb,
                               const float* __restrict__ bias_b)
{
    int warp = (blockIdx.x * blockDim.x + threadIdx.x) >> 5;
    int lane = threadIdx.x & 31;
    if (warp >= B_*H_*L_) return;
    int i = warp & (L_-1);
    int bh = warp >> 10;
    int h = bh & (H_-1), b = bh >> 3;
    const float* qrow = g_qs + ((size_t)(b*L_ + i)) * D_ + h*DK_;
    const float* w = Wqb + h*DK_;
    float s = qrow[lane]*w[lane] + qrow[lane+32]*w[lane+32];
#pragma unroll
    for (int o = 16; o; o >>= 1) s += __shfl_xor_sync(0xffffffffu, s, o);
    if (lane == 0)
        g_rowbias[warp] = (s + bqb[h] + bias_b[h]) * 0.125f;
}

// ---------------------------------------------------------------------------
// Qcat (fp32 SIMT): per (b,h): Qcat[i, n=t*64+c] = sum_d q_s[i,d]*Wker[h,c,t,d]
//  + bcat.  Writes bf16 hi/lo split. grid (4, 8, 64)
// ---------------------------------------------------------------------------
__global__ __launch_bounds__(256) void qcat_kernel(const float* __restrict__ Wker)
{
    const int z = blockIdx.z;
    const int b = z >> 3, h = z & 7;
    const int bm = blockIdx.y * 128;
    const int bn = blockIdx.x * 128;
    const int tid = threadIdx.x;
    const int ty = tid >> 4, tx = tid & 15;

    __shared__ float As[16][128];
    __shared__ float Bs[16][128];

    const float* A = g_qs + (size_t)b * L_ * D_ + h * DK_;
    const float* W = Wker + (size_t)h * DK_ * NCAT;

    float acc[8][8];
#pragma unroll
    for (int i = 0; i < 8; i++)
#pragma unroll
        for (int j = 0; j < 8; j++) acc[i][j] = 0.f;

    const int lr = tid >> 2, lc = (tid & 3) << 2;

    for (int k0 = 0; k0 < DK_; k0 += 16) {
#pragma unroll
        for (int s = 0; s < 2; s++) {
            int row = lr + s * 64;
            float4 va = *(const float4*)(A + (size_t)(bm + row) * D_ + k0 + lc);
            As[lc+0][row] = va.x; As[lc+1][row] = va.y;
            As[lc+2][row] = va.z; As[lc+3][row] = va.w;
        }
        for (int idx = tid; idx < 512; idx += 256) {
            int nloc = idx >> 2;
            int kl   = (idx & 3) << 2;
            int gn = bn + nloc;
            float4 vb = make_float4(0,0,0,0);
            if (gn < NCAT) {
                int t = gn >> 6, c = gn & 63;
                vb = *(const float4*)(W + (size_t)c * NCAT + t * DK_ + k0 + kl);
            }
            Bs[kl+0][nloc] = vb.x; Bs[kl+1][nloc] = vb.y;
            Bs[kl+2][nloc] = vb.z; Bs[kl+3][nloc] = vb.w;
        }
        __syncthreads();
#pragma unroll
        for (int kk = 0; kk < 16; kk++) {
            float ra[8], rb[8];
            *(float4*)(ra)   = *(const float4*)&As[kk][ty*8];
            *(float4*)(ra+4) = *(const float4*)&As[kk][ty*8+4];
            *(float4*)(rb)   = *(const float4*)&Bs[kk][tx*4];
            *(float4*)(rb+4) = *(const float4*)&Bs[kk][64 + tx*4];
#pragma unroll
            for (int i = 0; i < 8; i++)
#pragma unroll
                for (int j = 0; j < 8; j++)
                    acc[i][j] = fmaf(ra[i], rb[j], acc[i][j]);
        }
        __syncthreads();
    }

    __nv_bfloat16* Ch = g_qcat_hi + (size_t)z * L_ * NCAT;
    __nv_bfloat16* Cl = g_qcat_lo + (size_t)z * L_ * NCAT;
    int c0g = bn + tx*4, c1g = bn + 64 + tx*4;
    float4 b0 = make_float4(0,0,0,0), b1 = make_float4(0,0,0,0);
    if (c0g < NCAT) b0 = *(const float4*)(g_bcat + h*NCAT + c0g);
    if (c1g < NCAT) b1 = *(const float4*)(g_bcat + h*NCAT + c1g);
#pragma unroll
    for (int i = 0; i < 8; i++) {
        size_t ro = (size_t)(bm + ty*8 + i) * NCAT;
        if (c0g < NCAT) {
            float v0 = acc[i][0]+b0.x, v1 = acc[i][1]+b0.y;
            float v2 = acc[i][2]+b0.z, v3 = acc[i][3]+b0.w;
            float h0 = bhi(v0), h1 = bhi(v1), h2 = bhi(v2), h3 = bhi(v3);
            *(uint2*)(Ch + ro + c0g) = make_uint2(pk2(h0,h1), pk2(h2,h3));
            *(uint2*)(Cl + ro + c0g) = make_uint2(pk2(v0-h0,v1-h1), pk2(v2-h2,v3-h3));
        }
        if (c1g < NCAT) {
            float v0 = acc[i][4]+b1.x, v1 = acc[i][5]+b1.y;
            float v2 = acc[i][6]+b1.z, v3 = acc[i][7]+b1.w;
            float h0 = bhi(v0), h1 = bhi(v1), h2 = bhi(v2), h3 = bhi(v3);
            *(uint2*)(Ch + ro + c1g) = make_uint2(pk2(h0,h1), pk2(h2,h3));
            *(uint2*)(Cl + ro + c1g) = make_uint2(pk2(v0-h0,v1-h1), pk2(v2-h2,v3-h3));
        }
    }
}

// ---------------------------------------------------------------------------
// Kcat prep: Kcat[z][j][t*64+c] = k_s[b][j+t-3][h*64+c] ; bf16 hi/lo
// ---------------------------------------------------------------------------
__global__ __launch_bounds__(256) void kcat_prep_kernel()
{
    int idx = blockIdx.x * 256 + threadIdx.x;
    if (idx >= B_*H_*L_*(NCAT/8)) return;
    int c8 = idx % (NCAT/8);
    int rest = idx / (NCAT/8);
    int j = rest & (L_-1);
    int z = rest >> 10;
    int b = z >> 3, h = z & 7;
    int cpos = c8 * 8;
    int t = cpos >> 6, cc = cpos & 63;
    int src = j + t - PAD_;
    float4 v0 = make_float4(0,0,0,0), v1 = make_float4(0,0,0,0);
    if (src >= 0 && src < L_) {
        const float* p = g_ks + ((size_t)(b*L_ + src)) * D_ + h*DK_ + cc;
        v0 = *(const float4*)p;
        v1 = *(const float4*)(p + 4);
    }
    float f[8] = {v0.x, v0.y, v0.z, v0.w, v1.x, v1.y, v1.z, v1.w};
    float hh[8], ll[8];
#pragma unroll
    for (int i = 0; i < 8; i++) { hh[i] = bhi(f[i]); ll[i] = f[i] - hh[i]; }
    size_t off = (size_t)z * L_ * NCAT + (size_t)j * NCAT + cpos;
    *(uint4*)(g_kcat_hi + off) = make_uint4(pk2(hh[0],hh[1]), pk2(hh[2],hh[3]),
                                            pk2(hh[4],hh[5]), pk2(hh[6],hh[7]));
    *(uint4*)(g_kcat_lo + off) = make_uint4(pk2(ll[0],ll[1]), pk2(ll[2],ll[3]),
                                            pk2(ll[4],ll[5]), pk2(ll[6],ll[7]));
}

// ---------------------------------------------------------------------------
// vt transpose: vt[z][n][k] = v_s[b][k][h*64+n], bf16 hi/lo.
// grid (8 [k-tile 128], 64 [z]), 256 threads.
// ---------------------------------------------------------------------------
__global__ __launch_bounds__(256) void vt_kernel()
{
    __shared__ float t[128][65];
    const int z = blockIdx.y;
    const int b = z >> 3, h = z & 7;
    const int k0 = blockIdx.x * 128;
    const int tid = threadIdx.x;

#pragma unroll
    for (int q = 0; q < 8; q++) {
        int u = q * 256 + tid;
        int r = u >> 4, c4 = (u & 15) * 4;
        float4 v = *(const float4*)(g_vs + ((size_t)(b*L_ + k0 + r)) * D_ + h*DK_ + c4);
        t[r][c4+0] = v.x; t[r][c4+1] = v.y; t[r][c4+2] = v.z; t[r][c4+3] = v.w;
    }
    __syncthreads();

#pragma unroll
    for (int q = 0; q < 4; q++) {
        int u = q * 256 + tid;
        int n = u >> 4, kk = (u & 15) * 8;
        float f[8], hh[8], ll[8];
#pragma unroll
        for (int e = 0; e < 8; e++) f[e] = t[kk + e][n];
#pragma unroll
        for (int e = 0; e < 8; e++) { hh[e] = bhi(f[e]); ll[e] = f[e] - hh[e]; }
        size_t off = (size_t)z * DK_ * L_ + (size_t)n * L_ + k0 + kk;
        *(uint4*)(g_vt_hi + off) = make_uint4(pk2(hh[0],hh[1]), pk2(hh[2],hh[3]),
                                              pk2(hh[4],hh[5]), pk2(hh[6],hh[7]));
        *(uint4*)(g_vt_lo + off) = make_uint4(pk2(ll[0],ll[1]), pk2(ll[2],ll[3]),
                                              pk2(ll[4],ll[5]), pk2(ll[6],ll[7]));
    }
}

// ---------------------------------------------------------------------------
// Tensor-core logits (as R5, unchanged): 128x128 tile, K=448.
// ---------------------------------------------------------------------------
#define LOG_STAGE 32768
#define LOG_SMEM  (2*LOG_STAGE)

__global__ __launch_bounds__(256, 1) void logits_mma_kernel(float* __restrict__ attn)
{
    extern __shared__ char smem[];
    const uint32_t sbase = smem_u32(smem);

    const int tid  = threadIdx.x;
    const int wid  = tid >> 5, lane = tid & 31;
    const int wm   = wid >> 2, wn = wid & 3;

    const int z  = blockIdx.z;
    const int i0 = blockIdx.y * 128;
    const int j0 = blockIdx.x * 128;

    const __nv_bfloat16* qh = g_qcat_hi + (size_t)z * L_ * NCAT + (size_t)i0 * NCAT;
    const __nv_bfloat16* ql = g_qcat_lo + (size_t)z * L_ * NCAT + (size_t)i0 * NCAT;
    const __nv_bfloat16* kh = g_kcat_hi + (size_t)z * L_ * NCAT + (size_t)j0 * NCAT;
    const __nv_bfloat16* kl = g_kcat_lo + (size_t)z * L_ * NCAT + (size_t)j0 * NCAT;

    auto issue = [&](int s, int c) {
        const uint32_t sb = sbase + s * LOG_STAGE;
#pragma unroll
        for (int q = 0; q < 4; q++) {
            int u  = q * 256 + tid;
            int r  = u >> 3, cj = u & 7;
            const __nv_bfloat16* src =
                (cj < 4 ? qh : ql) + (size_t)r * NCAT + c * 32 + (cj & 3) * 8;
            CP_ASYNC16(sb + r * 128 + 16 * (cj ^ (r & 7)), src);
        }
#pragma unroll
        for (int q = 0; q < 4; q++) {
            int u  = q * 256 + tid;
            int r  = u >> 3, cj = u & 7;
            const __nv_bfloat16* src =
                (cj < 4 ? kh : kl) + (size_t)r * NCAT + c * 32 + (cj & 3) * 8;
            CP_ASYNC16(sb + 16384 + r * 128 + 16 * (cj ^ (r & 7)), src);
        }
    };

    float acc[4][4][4];
#pragma unroll
    for (int i = 0; i < 4; i++)
#pragma unroll
        for (int j = 0; j < 4; j++)
#pragma unroll
            for (int e = 0; e < 4; e++) acc[i][j][e] = 0.f;

    issue(0, 0);
    CP_COMMIT();

    const int lrow = (lane & 7) + 8 * ((lane >> 3) & 1);
    const int lchk = lane >> 4;

    for (int c = 0; c < 14; c++) {
        const int s = c & 1;
        if (c + 1 < 14) { issue(s ^ 1, c + 1); CP_COMMIT(); CP_WAIT(1); }
        else            { CP_WAIT(0); }
        __syncthreads();

        const uint32_t sA = sbase + s * LOG_STAGE;
        const uint32_t sB = sA + 16384;

#pragma unroll
        for (int ks = 0; ks < 2; ks++) {
            uint32_t bh[4][2], bl[4][2];
#pragma unroll
            for (int g = 0; g < 2; g++) {
                int r  = wn * 32 + g * 16 + lrow;
                int ch = ks * 2 + lchk;
                uint32_t r0, r1, r2, r3;
                LDSM4(r0, r1, r2, r3, sB + r * 128 + 16 * ((ch)     ^ (r & 7)));
                bh[2*g][0] = r0; bh[2*g][1] = r2;
                bh[2*g+1][0] = r1; bh[2*g+1][1] = r3;
                LDSM4(r0, r1, r2, r3, sB + r * 128 + 16 * ((ch + 4) ^ (r & 7)));
                bl[2*g][0] = r0; bl[2*g][1] = r2;
                bl[2*g+1][0] = r1; bl[2*g+1][1] = r3;
            }
#pragma unroll
            for (int mf = 0; mf < 4; mf++) {
                int r  = wm * 64 + mf * 16 + lrow;
                int ch = ks * 2 + lchk;
                uint32_t ah[4], al[4];
                LDSM4(ah[0], ah[1], ah[2], ah[3],
                      sA + r * 128 + 16 * ((ch)     ^ (r & 7)));
                LDSM4(al[0], al[1], al[2], al[3],
                      sA + r * 128 + 16 * ((ch + 4) ^ (r & 7)));
#pragma unroll
                for (int nf = 0; nf < 4; nf++) {
                    MMA16816(acc[mf][nf], ah, bh[nf]);
                    MMA16816(acc[mf][nf], ah, bl[nf]);
                    MMA16816(acc[mf][nf], al, bh[nf]);
                }
            }
        }
        __syncthreads();
    }

    const int rbase = i0 + wm * 64 + (lane >> 2);
    const int cbase = j0 + wn * 32 + 2 * (lane & 3);
#pragma unroll
    for (int mf = 0; mf < 4; mf++) {
        int gi0 = rbase + mf * 16;
        float rb0 = g_rowbias[(size_t)z * L_ + gi0];
        float rb1 = g_rowbias[(size_t)z * L_ + gi0 + 8];
        float* row0 = attn + ((size_t)z * L_ + gi0) * L_;
        float* row1 = row0 + 8 * L_;
#pragma unroll
        for (int nf = 0; nf < 4; nf++) {
            int gj = cbase + nf * 8;
            *(float2*)(row0 + gj) = make_float2(acc[mf][nf][0]*0.125f + rb0,
                                                acc[mf][nf][1]*0.125f + rb0);
            *(float2*)(row1 + gj) = make_float2(acc[mf][nf][2]*0.125f + rb1,
                                                acc[mf][nf][3]*0.125f + rb1);
        }
    }
}

// ---------------------------------------------------------------------------
// Row softmax in-place on attn; mask; head-0 duplicate.
// ---------------------------------------------------------------------------
__global__ __launch_bounds__(256) void softmax_kernel(
    float* __restrict__ attn, const unsigned char* __restrict__ mask,
    float* __restrict__ one_head)
{
    const int r = blockIdx.x;
    const int i = r & (L_-1);
    const int bh = r >> 10;
    const int h = bh & (H_-1), b = bh >> 3;
    float* row = attn + (size_t)r * L_;
    const unsigned char* mrow = mask + ((size_t)(b*L_ + i)) * L_;
    const int t4 = threadIdx.x * 4;

    float4 v = *(const float4*)(row + t4);
    uchar4 m = *(const uchar4*)(mrow + t4);
    float x0 = m.x ? -INFINITY : v.x;
    float x1 = m.y ? -INFINITY : v.y;
    float x2 = m.z ? -INFINITY : v.z;
    float x3 = m.w ? -INFINITY : v.w;

    __shared__ float sm[8], ss[8];
    float mx = fmaxf(fmaxf(x0, x1), fmaxf(x2, x3));
#pragma unroll
    for (int o = 16; o; o >>= 1) mx = fmaxf(mx, __shfl_xor_sync(0xffffffffu, mx, o));
    if ((threadIdx.x & 31) == 0) sm[threadIdx.x >> 5] = mx;
    __syncthreads();
    if (threadIdx.x < 32) {
        float t = (threadIdx.x < 8) ? sm[threadIdx.x] : -INFINITY;
#pragma unroll
        for (int o = 4; o; o >>= 1) t = fmaxf(t, __shfl_xor_sync(0xffffffffu, t, o));
        if (threadIdx.x == 0) sm[0] = t;
    }
    __syncthreads();
    mx = sm[0];

    float e0 = __expf(x0 - mx), e1 = __expf(x1 - mx);
    float e2 = __expf(x2 - mx), e3 = __expf(x3 - mx);
    float s = (e0 + e1) + (e2 + e3);
#pragma unroll
    for (int o = 16; o; o >>= 1) s += __shfl_xor_sync(0xffffffffu, s, o);
    if ((threadIdx.x & 31) == 0) ss[threadIdx.x >> 5] = s;
    __syncthreads();
    if (threadIdx.x < 32) {
        float t = (threadIdx.x < 8) ? ss[threadIdx.x] : 0.f;
#pragma unroll
        for (int o = 4; o; o >>= 1) t += __shfl_xor_sync(0xffffffffu, t, o);
        if (threadIdx.x == 0) ss[0] = t;
    }
    __syncthreads();
    float inv = 1.0f / ss[0];

    float4 o = make_float4(e0*inv, e1*inv, e2*inv, e3*inv);
    *(float4*)(row + t4) = o;
    if (h == 0)
        *(float4*)(one_head + ((size_t)(b*L_ + i)) * L_ + t4) = o;
}

// ---------------------------------------------------------------------------
// ctx via mma: per (b,h): C[1024,64] = attn @ v_head.
// A = attn fp32 (LDG + hi/lo split in-kernel), B = g_vt hi/lo [64,1024].
// Writes g_ctx_hi/lo at [B*L, 512] (head = col slice).
// grid (8 [i-tile], 64 [z]), 256 threads, 48KB static smem.
// Warp layout 2(m) x 4(n): warp tile 64 x 16.
// ---------------------------------------------------------------------------
#define CTX_STAGE 24576   /* A 16KB + B 8KB */

__global__ __launch_bounds__(256, 1) void ctx_mma_kernel(const float* __restrict__ attn)
{
    __shared__ char smem[2 * CTX_STAGE];
    const uint32_t sbase = smem_u32(smem);

    const int tid  = threadIdx.x;
    const int wid  = tid >> 5, lane = tid & 31;
    const int wm   = wid >> 2, wn = wid & 3;

    const int z  = blockIdx.y;
    const int b = z >> 3, h = z & 7;
    const int i0 = blockIdx.x * 128;

    const float* A = attn + ((size_t)z * L_ + i0) * L_;
    const __nv_bfloat16* vh = g_vt_hi + (size_t)z * DK_ * L_;
    const __nv_bfloat16* vl = g_vt_lo + (size_t)z * DK_ * L_;

    // B loader (cp.async): 64 rows x 8 cj
    auto issueB = [&](int s, int c) {
        const uint32_t sb = sbase + s * CTX_STAGE + 16384;
#pragma unroll
        for (int q = 0; q < 2; q++) {
            int u  = q * 256 + tid;
            int r  = u >> 3, cj = u & 7;
            const __nv_bfloat16* src =
                (cj < 4 ? vh : vl) + (size_t)r * L_ + c * 32 + (cj & 3) * 8;
            CP_ASYNC16(sb + r * 128 + 16 * (cj ^ (r & 7)), src);
        }
    };
    // A register prefetch: 2 units x 8 floats
    float fa[2][8];
    auto ldgA = [&](int c) {
#pragma unroll
        for (int q = 0; q < 2; q++) {
            int u = q * 256 + tid;
            int r = u >> 2, seg = u & 3;
            const float4* p = (const float4*)(A + (size_t)r * L_ + c * 32 + seg * 8);
            float4 v0 = p[0], v1 = p[1];
            fa[q][0]=v0.x; fa[q][1]=v0.y; fa[q][2]=v0.z; fa[q][3]=v0.w;
            fa[q][4]=v1.x; fa[q][5]=v1.y; fa[q][6]=v1.z; fa[q][7]=v1.w;
        }
    };
    auto stsA = [&](int s) {
        const uint32_t sb = sbase + s * CTX_STAGE;
#pragma unroll
        for (int q = 0; q < 2; q++) {
            int u = q * 256 + tid;
            int r = u >> 2, seg = u & 3;
            float hh[8], ll[8];
#pragma unroll
            for (int e = 0; e < 8; e++) { hh[e] = bhi(fa[q][e]); ll[e] = fa[q][e] - hh[e]; }
            uint4 whi = make_uint4(pk2(hh[0],hh[1]), pk2(hh[2],hh[3]),
                                   pk2(hh[4],hh[5]), pk2(hh[6],hh[7]));
            uint4 wlo = make_uint4(pk2(ll[0],ll[1]), pk2(ll[2],ll[3]),
                                   pk2(ll[4],ll[5]), pk2(ll[6],ll[7]));
            *(uint4*)(smem + s * CTX_STAGE + r * 128 + 16 * ((seg)     ^ (r & 7))) = whi;
            *(uint4*)(smem + s * CTX_STAGE + r * 128 + 16 * ((seg + 4) ^ (r & 7))) = wlo;
        }
    };

    float acc[4][2][4];
#pragma unroll
    for (int i = 0; i < 4; i++)
#pragma unroll
        for (int j = 0; j < 2; j++)
#pragma unroll
            for (int e = 0; e < 4; e++) acc[i][j][e] = 0.f;

    ldgA(0);
    issueB(0, 0); CP_COMMIT();

    const int lrow = (lane & 7) + 8 * ((lane >> 3) & 1);
    const int lchk = lane >> 4;

    for (int c = 0; c < 32; c++) {
        const int s = c & 1;
        stsA(s);
        if (c + 1 < 32) {
            ldgA(c + 1);
            issueB(s ^ 1, c + 1); CP_COMMIT(); CP_WAIT(1);
        } else {
            CP_WAIT(0);
        }
        __syncthreads();

        const uint32_t sA = sbase + s * CTX_STAGE;
        const uint32_t sB = sA + 16384;

#pragma unroll
        for (int ks = 0; ks < 2; ks++) {
            uint32_t bh[2][2], bl[2][2];
            {
                int r  = wn * 16 + lrow;
                int ch = ks * 2 + lchk;
                uint32_t r0, r1, r2, r3;
                LDSM4(r0, r1, r2, r3, sB + r * 128 + 16 * ((ch)     ^ (r & 7)));
                bh[0][0] = r0; bh[0][1] = r2; bh[1][0] = r1; bh[1][1] = r3;
                LDSM4(r0, r1, r2, r3, sB + r * 128 + 16 * ((ch + 4) ^ (r & 7)));
                bl[0][0] = r0; bl[0][1] = r2; bl[1][0] = r1; bl[1][1] = r3;
            }
#pragma unroll
            for (int mf = 0; mf < 4; mf++) {
                int r  = wm * 64 + mf * 16 + lrow;
                int ch = ks * 2 + lchk;
                uint32_t ah[4], al[4];
                LDSM4(ah[0], ah[1], ah[2], ah[3],
                      sA + r * 128 + 16 * ((ch)     ^ (r & 7)));
                LDSM4(al[0], al[1], al[2], al[3],
                      sA + r * 128 + 16 * ((ch + 4) ^ (r & 7)));
#pragma unroll
                for (int nf = 0; nf < 2; nf++) {
                    MMA16816(acc[mf][nf], ah, bh[nf]);
                    MMA16816(acc[mf][nf], ah, bl[nf]);
                    MMA16816(acc[mf][nf], al, bh[nf]);
                }
            }
        }
        __syncthreads();
    }

    // epilogue: ctx hi/lo at [B*L, 512]
    const int rbase = i0 + wm * 64 + (lane >> 2);
    const int cb = h * DK_ + wn * 16 + 2 * (lane & 3);
#pragma unroll
    for (int mf = 0; mf < 4; mf++) {
        int gi = rbase + mf * 16;
        size_t ro0 = ((size_t)(b * L_) + gi) * D_;
        size_t ro1 = ro0 + 8 * D_;
#pragma unroll
        for (int nf = 0; nf < 2; nf++) {
            int gj = cb + nf * 8;
            float v0 = acc[mf][nf][0], v1 = acc[mf][nf][1];
            float v2 = acc[mf][nf][2], v3 = acc[mf][nf][3];
            float h0 = bhi(v0), h1 = bhi(v1), h2 = bhi(v2), h3 = bhi(v3);
            *(unsigned*)(g_ctx_hi + ro0 + gj) = pk2(h0, h1);
            *(unsigned*)(g_ctx_lo + ro0 + gj) = pk2(v0 - h0, v1 - h1);
            *(unsigned*)(g_ctx_hi + ro1 + gj) = pk2(h2, h3);
            *(unsigned*)(g_ctx_lo + ro1 + gj) = pk2(v2 - h2, v3 - h3);
        }
    }
}

// ---------------------------------------------------------------------------
extern "C" void kernel_launch(void* const* d_in, const int* in_sizes, int n_in,
                              void* d_out, int out_size)
{
    const float* q      = (const float*)d_in[0];
    const float* k      = (const float*)d_in[1];
    const float* v      = (const float*)d_in[2];
    const unsigned char* mask = (const unsigned char*)d_in[3];
    const float* Wq     = (const float*)d_in[4];
    const float* bq     = (const float*)d_in[5];
    const float* Wk     = (const float*)d_in[6];
    const float* bk     = (const float*)d_in[7];
    const float* Wv     = (const float*)d_in[8];
    const float* bv     = (const float*)d_in[9];
    const float* Wker   = (const float*)d_in[10];
    const float* bker   = (const float*)d_in[11];
    const float* Wqb    = (const float*)d_in[12];
    const float* bqb    = (const float*)d_in[13];
    const float* bias_b = (const float*)d_in[14];
    const float* Wproj  = (const float*)d_in[15];
    const float* bproj  = (const float*)d_in[16];

    float* out      = (float*)d_out;
    float* attn     = out + (size_t)B_ * L_ * D_;
    float* one_head = attn + (size_t)B_ * H_ * L_ * L_;

    void* p;
    cudaGetSymbolAddress(&p, g_qs);  float* qs  = (float*)p;
    cudaGetSymbolAddress(&p, g_ks);  float* ks  = (float*)p;
    cudaGetSymbolAddress(&p, g_vs);  float* vs  = (float*)p;
    __nv_bfloat16 *qh, *ql, *kh, *kl, *vh, *vl, *wh, *wl, *ch, *cl;
    cudaGetSymbolAddress(&p, g_inq_hi); qh = (__nv_bfloat16*)p;
    cudaGetSymbolAddress(&p, g_inq_lo); ql = (__nv_bfloat16*)p;
    cudaGetSymbolAddress(&p, g_ink_hi); kh = (__nv_bfloat16*)p;
    cudaGetSymbolAddress(&p, g_ink_lo); kl = (__nv_bfloat16*)p;
    cudaGetSymbolAddress(&p, g_inv_hi); vh = (__nv_bfloat16*)p;
    cudaGetSymbolAddress(&p, g_inv_lo); vl = (__nv_bfloat16*)p;
    cudaGetSymbolAddress(&p, g_w_hi);   wh = (__nv_bfloat16*)p;
    cudaGetSymbolAddress(&p, g_w_lo);   wl = (__nv_bfloat16*)p;
    cudaGetSymbolAddress(&p, g_ctx_hi); ch = (__nv_bfloat16*)p;
    cudaGetSymbolAddress(&p, g_ctx_lo); cl = (__nv_bfloat16*)p;

    static bool attr_done = false;
    if (!attr_done) {
        cudaFuncSetAttribute(logits_mma_kernel,
            cudaFuncAttributeMaxDynamicSharedMemorySize, LOG_SMEM);
        cudaFuncSetAttribute(gemm_mma_nt,
            cudaFuncAttributeMaxDynamicSharedMemorySize, GM_SMEM);
        attr_done = true;
    }

    const int M = B_ * L_;        // 8192
    const int NE = M * D_;        // 4194304
    const int NW = D_ * D_;       // 262144
    dim3 blk(256);

    // 0) split inputs + weights to bf16 hi/lo
    conv_split_kernel<<<(NE/8 + 255)/256, 256>>>(q, qh, ql, NE/8);
    conv_split_kernel<<<(NE/8 + 255)/256, 256>>>(k, kh, kl, NE/8);
    conv_split_kernel<<<(NE/8 + 255)/256, 256>>>(v, vh, vl, NE/8);
    conv_split_kernel<<<(NW/8 + 255)/256, 256>>>(Wq,    wh,        wl,        NW/8);
    conv_split_kernel<<<(NW/8 + 255)/256, 256>>>(Wk,    wh + NW,   wl + NW,   NW/8);
    conv_split_kernel<<<(NW/8 + 255)/256, 256>>>(Wv,    wh + 2*NW, wl + 2*NW, NW/8);
    conv_split_kernel<<<(NW/8 + 255)/256, 256>>>(Wproj, wh + 3*NW, wl + 3*NW, NW/8);

    // 1) projections (tensor cores)
    gemm_mma_nt<<<dim3(D_/128, M/128), blk, GM_SMEM>>>(qh, ql, wh,        wl,        bq, qs, D_, D_);
    gemm_mma_nt<<<dim3(D_/128, M/128), blk, GM_SMEM>>>(kh, kl, wh + NW,   wl + NW,   bk, ks, D_, D_);
    gemm_mma_nt<<<dim3(D_/128, M/128), blk, GM_SMEM>>>(vh, vl, wh + 2*NW, wl + 2*NW, bv, vs, D_, D_);

    // 2) folded biases
    bcat_kernel<<<(H_*NCAT + 255)/256, 256>>>(bker);
    rowbias_kernel<<<(B_*H_*L_*32)/256, 256>>>(Wqb, bqb, bias_b);

    // 3) operand prep
    qcat_kernel<<<dim3(4, L_/128, B_*H_), blk>>>(Wker);
    kcat_prep_kernel<<<(B_*H_*L_*(NCAT/8) + 255)/256, 256>>>();
    vt_kernel<<<dim3(L_/128, B_*H_), blk>>>();

    // 4) tensor-core logits -> attn region
    logits_mma_kernel<<<dim3(L_/128, L_/128, B_*H_), 256, LOG_SMEM>>>(attn);

    // 5) softmax in place (+ one_head copy)
    softmax_kernel<<<B_*H_*L_, 256>>>(attn, mask, one_head);

    // 6) ctx = attn @ v_s (tensor cores) -> g_ctx hi/lo
    ctx_mma_kernel<<<dim3(L_/128, B_*H_), blk>>>(attn);

    // 7) out = ctx @ Wproj^T + bproj (tensor cores)
    gemm_mma_nt<<<dim3(D_/128, M/128), blk, GM_SMEM>>>(ch, cl, wh + 3*NW, wl + 3*NW, bproj, out, D_, D_);
}